// round 1
// baseline (speedup 1.0000x reference)
#include <cuda_runtime.h>

// ---------------------------------------------------------------------------
// RWKV-v4 forward, 6 layers. B=4, T=2048, H=A=1024, I=4096.
// Baseline: fp32 SIMT GEMMs (128x128x16 tiles), per-channel sequential WKV.
// ---------------------------------------------------------------------------

#define Bz 4
#define Tt 2048
#define Hh 1024
#define Av 1024
#define Iv 4096
#define Lv 6
#define BT (Bz * Tt)                 // 8192 rows
#define SROW ((size_t)BT * Hh)       // 8388608 floats per [BT,H] buffer

// Scratch: h, x, xk, xv, xr, ry, k, v, r, y  (10 * SROW)  +  kk (BT*Iv)
__device__ float g_buf[10 * 8388608 + (size_t)BT * Iv];

// ---------------------------------------------------------------------------
// LayerNorm: one block per row, 256 threads, H=1024 (one float4 per thread)
// ---------------------------------------------------------------------------
__global__ __launch_bounds__(256) void ln_kernel(
    const float* __restrict__ in, float* __restrict__ out,
    const float* __restrict__ w, const float* __restrict__ b)
{
    const int n = blockIdx.x;
    const int tid = threadIdx.x;
    const float4 xv = ((const float4*)(in + (size_t)n * Hh))[tid];
    float s  = xv.x + xv.y + xv.z + xv.w;
    float sq = xv.x * xv.x + xv.y * xv.y + xv.z * xv.z + xv.w * xv.w;
#pragma unroll
    for (int o = 16; o; o >>= 1) {
        s  += __shfl_xor_sync(0xffffffffu, s,  o);
        sq += __shfl_xor_sync(0xffffffffu, sq, o);
    }
    __shared__ float ss[8], sqs[8];
    if ((tid & 31) == 0) { ss[tid >> 5] = s; sqs[tid >> 5] = sq; }
    __syncthreads();
    s = 0.f; sq = 0.f;
#pragma unroll
    for (int i = 0; i < 8; i++) { s += ss[i]; sq += sqs[i]; }
    const float mu  = s * (1.0f / Hh);
    const float var = sq * (1.0f / Hh) - mu * mu;
    const float rstd = rsqrtf(var + 1e-5f);
    const float4 w4 = ((const float4*)w)[tid];
    const float4 b4 = ((const float4*)b)[tid];
    float4 o4;
    o4.x = (xv.x - mu) * rstd * w4.x + b4.x;
    o4.y = (xv.y - mu) * rstd * w4.y + b4.y;
    o4.z = (xv.z - mu) * rstd * w4.z + b4.z;
    o4.w = (xv.w - mu) * rstd * w4.w + b4.w;
    ((float4*)(out + (size_t)n * Hh))[tid] = o4;
}

// Embedding gather + pre-LN fused
__global__ __launch_bounds__(256) void embed_ln_kernel(
    const int* __restrict__ ids, const float* __restrict__ embed,
    const float* __restrict__ w, const float* __restrict__ b,
    float* __restrict__ out)
{
    const int n = blockIdx.x;
    const int tid = threadIdx.x;
    const int id = ids[n];
    const float4 xv = ((const float4*)(embed + (size_t)id * Hh))[tid];
    float s  = xv.x + xv.y + xv.z + xv.w;
    float sq = xv.x * xv.x + xv.y * xv.y + xv.z * xv.z + xv.w * xv.w;
#pragma unroll
    for (int o = 16; o; o >>= 1) {
        s  += __shfl_xor_sync(0xffffffffu, s,  o);
        sq += __shfl_xor_sync(0xffffffffu, sq, o);
    }
    __shared__ float ss[8], sqs[8];
    if ((tid & 31) == 0) { ss[tid >> 5] = s; sqs[tid >> 5] = sq; }
    __syncthreads();
    s = 0.f; sq = 0.f;
#pragma unroll
    for (int i = 0; i < 8; i++) { s += ss[i]; sq += sqs[i]; }
    const float mu  = s * (1.0f / Hh);
    const float var = sq * (1.0f / Hh) - mu * mu;
    const float rstd = rsqrtf(var + 1e-5f);
    const float4 w4 = ((const float4*)w)[tid];
    const float4 b4 = ((const float4*)b)[tid];
    float4 o4;
    o4.x = (xv.x - mu) * rstd * w4.x + b4.x;
    o4.y = (xv.y - mu) * rstd * w4.y + b4.y;
    o4.z = (xv.z - mu) * rstd * w4.z + b4.z;
    o4.w = (xv.w - mu) * rstd * w4.w + b4.w;
    ((float4*)(out + (size_t)n * Hh))[tid] = o4;
}

// ---------------------------------------------------------------------------
// Token-shift mixing.  mix*x + (1-mix)*prev  ==  prev + mix*(x - prev)
// idx indexes float4 elements; H/4 = 256 float4 per row.
// ---------------------------------------------------------------------------
__global__ __launch_bounds__(256) void mix3_kernel(
    const float* __restrict__ x,
    const float* __restrict__ mk, const float* __restrict__ mv, const float* __restrict__ mr,
    float* __restrict__ xk, float* __restrict__ xv, float* __restrict__ xr)
{
    const int idx = blockIdx.x * 256 + threadIdx.x;   // float4 index
    const int n  = idx >> 8;
    const int j4 = idx & 255;
    const int t  = n & (Tt - 1);
    const float4 cur = ((const float4*)x)[idx];
    float4 prev = make_float4(0.f, 0.f, 0.f, 0.f);
    if (t > 0) prev = ((const float4*)x)[idx - 256];
    const float4 k4 = ((const float4*)mk)[j4];
    const float4 v4 = ((const float4*)mv)[j4];
    const float4 r4 = ((const float4*)mr)[j4];
    float4 o;
    o.x = prev.x + k4.x * (cur.x - prev.x); o.y = prev.y + k4.y * (cur.y - prev.y);
    o.z = prev.z + k4.z * (cur.z - prev.z); o.w = prev.w + k4.w * (cur.w - prev.w);
    ((float4*)xk)[idx] = o;
    o.x = prev.x + v4.x * (cur.x - prev.x); o.y = prev.y + v4.y * (cur.y - prev.y);
    o.z = prev.z + v4.z * (cur.z - prev.z); o.w = prev.w + v4.w * (cur.w - prev.w);
    ((float4*)xv)[idx] = o;
    o.x = prev.x + r4.x * (cur.x - prev.x); o.y = prev.y + r4.y * (cur.y - prev.y);
    o.z = prev.z + r4.z * (cur.z - prev.z); o.w = prev.w + r4.w * (cur.w - prev.w);
    ((float4*)xr)[idx] = o;
}

__global__ __launch_bounds__(256) void mix2_kernel(
    const float* __restrict__ x,
    const float* __restrict__ mk, const float* __restrict__ mr,
    float* __restrict__ xk, float* __restrict__ xr)
{
    const int idx = blockIdx.x * 256 + threadIdx.x;
    const int n  = idx >> 8;
    const int j4 = idx & 255;
    const int t  = n & (Tt - 1);
    const float4 cur = ((const float4*)x)[idx];
    float4 prev = make_float4(0.f, 0.f, 0.f, 0.f);
    if (t > 0) prev = ((const float4*)x)[idx - 256];
    const float4 k4 = ((const float4*)mk)[j4];
    const float4 r4 = ((const float4*)mr)[j4];
    float4 o;
    o.x = prev.x + k4.x * (cur.x - prev.x); o.y = prev.y + k4.y * (cur.y - prev.y);
    o.z = prev.z + k4.z * (cur.z - prev.z); o.w = prev.w + k4.w * (cur.w - prev.w);
    ((float4*)xk)[idx] = o;
    o.x = prev.x + r4.x * (cur.x - prev.x); o.y = prev.y + r4.y * (cur.y - prev.y);
    o.z = prev.z + r4.z * (cur.z - prev.z); o.w = prev.w + r4.w * (cur.w - prev.w);
    ((float4*)xr)[idx] = o;
}

// ---------------------------------------------------------------------------
// WKV recurrence: one thread per (batch, channel), sequential over T.
// ---------------------------------------------------------------------------
__global__ __launch_bounds__(128) void wkv_kernel(
    const float* __restrict__ k, const float* __restrict__ v,
    float* __restrict__ y,
    const float* __restrict__ tf, const float* __restrict__ td)
{
    const int idx = blockIdx.x * 128 + threadIdx.x;   // 0..4095
    const int b  = idx >> 10;
    const int ch = idx & (Av - 1);
    const float u = tf[ch];
    const float w = -__expf(td[ch]);
    const float* kp = k + (size_t)b * Tt * Av + ch;
    const float* vp = v + (size_t)b * Tt * Av + ch;
    float*       yp = y + (size_t)b * Tt * Av + ch;
    float aa = 0.f, bb = 0.f, p = -1e38f;
    for (int t = 0; t < Tt; t++) {
        const float kt = kp[(size_t)t * Av];
        const float vt = vp[(size_t)t * Av];
        const float uk = u + kt;
        const float q  = fmaxf(p, uk);
        const float e1 = __expf(p - q);
        const float e2 = __expf(uk - q);
        yp[(size_t)t * Av] = __fdividef(aa * e1 + e2 * vt, bb * e1 + e2);
        const float pw = p + w;
        const float q2 = fmaxf(pw, kt);
        const float s1 = __expf(pw - q2);
        const float s2 = __expf(kt - q2);
        aa = s1 * aa + s2 * vt;
        bb = s1 * bb + s2;
        p  = q2;
    }
}

// ry = sigmoid-applied r (already) * y
__global__ __launch_bounds__(256) void rymul_kernel(
    const float* __restrict__ r, const float* __restrict__ y, float* __restrict__ ry)
{
    const int idx = blockIdx.x * 256 + threadIdx.x;
    const float4 a = ((const float4*)r)[idx];
    const float4 c = ((const float4*)y)[idx];
    float4 o;
    o.x = a.x * c.x; o.y = a.y * c.y; o.z = a.z * c.z; o.w = a.w * c.w;
    ((float4*)ry)[idx] = o;
}

// ---------------------------------------------------------------------------
// SGEMM  C[M,N] (op)= A[M,K] * B[N,K]^T    (both operands K-major / "NT")
// 128x128 block tile, 8x8 per thread, BK=16, 256 threads.
// EPI: 0 store, 1 sigmoid, 2 relu^2, 3 C+=acc, 4 C+=S*acc
// M,N,K assumed multiples of 128/16 (true for all calls here).
// ---------------------------------------------------------------------------
template <int EPI>
__global__ __launch_bounds__(256) void gemm_nt(
    const float* __restrict__ A, const float* __restrict__ B,
    float* __restrict__ C, const float* __restrict__ Sb,
    int M, int N, int K)
{
    __shared__ float As[16][128];
    __shared__ float Bs[16][128];
    const int tid = threadIdx.x;
    const int lr  = tid >> 2;          // 0..63
    const int lc  = (tid & 3) * 4;     // 0,4,8,12
    const int tx  = tid & 15;
    const int ty  = tid >> 4;
    const float* Ag = A + (size_t)blockIdx.y * 128 * K;
    const float* Bg = B + (size_t)blockIdx.x * 128 * K;

    float acc[8][8];
#pragma unroll
    for (int i = 0; i < 8; i++)
#pragma unroll
        for (int j = 0; j < 8; j++) acc[i][j] = 0.f;

    for (int k0 = 0; k0 < K; k0 += 16) {
        const float4 a0 = *(const float4*)(Ag + (size_t)lr * K + k0 + lc);
        const float4 a1 = *(const float4*)(Ag + (size_t)(lr + 64) * K + k0 + lc);
        const float4 b0 = *(const float4*)(Bg + (size_t)lr * K + k0 + lc);
        const float4 b1 = *(const float4*)(Bg + (size_t)(lr + 64) * K + k0 + lc);
        __syncthreads();
        As[lc + 0][lr] = a0.x; As[lc + 1][lr] = a0.y; As[lc + 2][lr] = a0.z; As[lc + 3][lr] = a0.w;
        As[lc + 0][lr + 64] = a1.x; As[lc + 1][lr + 64] = a1.y; As[lc + 2][lr + 64] = a1.z; As[lc + 3][lr + 64] = a1.w;
        Bs[lc + 0][lr] = b0.x; Bs[lc + 1][lr] = b0.y; Bs[lc + 2][lr] = b0.z; Bs[lc + 3][lr] = b0.w;
        Bs[lc + 0][lr + 64] = b1.x; Bs[lc + 1][lr + 64] = b1.y; Bs[lc + 2][lr + 64] = b1.z; Bs[lc + 3][lr + 64] = b1.w;
        __syncthreads();
#pragma unroll
        for (int kk = 0; kk < 16; kk++) {
            float ar[8], br[8];
            *(float4*)(ar)     = *(const float4*)(&As[kk][ty * 8]);
            *(float4*)(ar + 4) = *(const float4*)(&As[kk][ty * 8 + 4]);
            *(float4*)(br)     = *(const float4*)(&Bs[kk][tx * 8]);
            *(float4*)(br + 4) = *(const float4*)(&Bs[kk][tx * 8 + 4]);
#pragma unroll
            for (int i = 0; i < 8; i++)
#pragma unroll
                for (int j = 0; j < 8; j++) acc[i][j] += ar[i] * br[j];
        }
    }

#pragma unroll
    for (int i = 0; i < 8; i++) {
        const size_t row = (size_t)blockIdx.y * 128 + ty * 8 + i;
        float* Crow = C + row * N + blockIdx.x * 128 + tx * 8;
        const float* Srow = (EPI == 4) ? (Sb + row * N + blockIdx.x * 128 + tx * 8) : nullptr;
#pragma unroll
        for (int j = 0; j < 8; j++) {
            const float vacc = acc[i][j];
            if (EPI == 0)      Crow[j] = vacc;
            else if (EPI == 1) Crow[j] = 1.f / (1.f + __expf(-vacc));
            else if (EPI == 2) { const float t = fmaxf(vacc, 0.f); Crow[j] = t * t; }
            else if (EPI == 3) Crow[j] += vacc;
            else               Crow[j] += Srow[j] * vacc;
        }
    }
}

// ---------------------------------------------------------------------------
// Host launcher
// ---------------------------------------------------------------------------
extern "C" void kernel_launch(void* const* d_in, const int* in_sizes, int n_in,
                              void* d_out, int out_size)
{
    const int*   ids    = (const int*)  d_in[0];
    const float* embed  = (const float*)d_in[1];
    const float* pre_w  = (const float*)d_in[2];
    const float* pre_b  = (const float*)d_in[3];
    const float* post_w = (const float*)d_in[4];
    const float* post_b = (const float*)d_in[5];
    const float* ln1_w  = (const float*)d_in[6];
    const float* ln1_b  = (const float*)d_in[7];
    const float* ln2_w  = (const float*)d_in[8];
    const float* ln2_b  = (const float*)d_in[9];
    const float* amk    = (const float*)d_in[10];
    const float* amv    = (const float*)d_in[11];
    const float* amr    = (const float*)d_in[12];
    const float* awk    = (const float*)d_in[13];
    const float* awv    = (const float*)d_in[14];
    const float* awr    = (const float*)d_in[15];
    const float* awo    = (const float*)d_in[16];
    const float* tdec   = (const float*)d_in[17];
    const float* tfirst = (const float*)d_in[18];
    const float* fmk    = (const float*)d_in[19];
    const float* fmr    = (const float*)d_in[20];
    const float* fwk    = (const float*)d_in[21];
    const float* fwr    = (const float*)d_in[22];
    const float* fwv    = (const float*)d_in[23];

    float* base = nullptr;
    cudaGetSymbolAddress((void**)&base, g_buf);
    float* h   = base;
    float* x   = base + 1 * SROW;
    float* xk  = base + 2 * SROW;
    float* xv  = base + 3 * SROW;
    float* xr  = base + 4 * SROW;
    float* ry  = base + 5 * SROW;
    float* kb  = base + 6 * SROW;
    float* vb  = base + 7 * SROW;
    float* rb  = base + 8 * SROW;
    float* yb  = base + 9 * SROW;
    float* kkb = base + 10 * SROW;

    const int EW_BLOCKS = (BT * Hh / 4) / 256;   // 8192
    const dim3 gA(Av / 128, BT / 128);
    const dim3 gH(Hh / 128, BT / 128);
    const dim3 gI(Iv / 128, BT / 128);

    embed_ln_kernel<<<BT, 256>>>(ids, embed, pre_w, pre_b, h);

    for (int i = 0; i < Lv; i++) {
        // --- attention (time mixing) ---
        ln_kernel<<<BT, 256>>>(h, x, ln1_w + i * Hh, ln1_b + i * Hh);
        mix3_kernel<<<EW_BLOCKS, 256>>>(x, amk + i * Hh, amv + i * Hh, amr + i * Hh,
                                        xk, xv, xr);
        gemm_nt<0><<<gA, 256>>>(xk, awk + (size_t)i * Av * Hh, kb, nullptr, BT, Av, Hh);
        gemm_nt<0><<<gA, 256>>>(xv, awv + (size_t)i * Av * Hh, vb, nullptr, BT, Av, Hh);
        gemm_nt<1><<<gA, 256>>>(xr, awr + (size_t)i * Av * Hh, rb, nullptr, BT, Av, Hh);
        wkv_kernel<<<32, 128>>>(kb, vb, yb, tfirst + i * Av, tdec + i * Av);
        rymul_kernel<<<EW_BLOCKS, 256>>>(rb, yb, ry);
        gemm_nt<3><<<gH, 256>>>(ry, awo + (size_t)i * Hh * Av, h, nullptr, BT, Hh, Av);

        // --- feed forward (channel mixing) ---
        ln_kernel<<<BT, 256>>>(h, x, ln2_w + i * Hh, ln2_b + i * Hh);
        mix2_kernel<<<EW_BLOCKS, 256>>>(x, fmk + i * Hh, fmr + i * Hh, xk, xr);
        gemm_nt<2><<<gI, 256>>>(xk, fwk + (size_t)i * Iv * Hh, kkb, nullptr, BT, Iv, Hh);
        gemm_nt<1><<<gH, 256>>>(xr, fwr + (size_t)i * Hh * Hh, rb, nullptr, BT, Hh, Hh);
        gemm_nt<4><<<gH, 256>>>(kkb, fwv + (size_t)i * Hh * Iv, h, rb, BT, Hh, Iv);
    }

    ln_kernel<<<BT, 256>>>(h, (float*)d_out, post_w, post_b);
}

// round 8
// speedup vs baseline: 2.5499x; 2.5499x over previous
#include <cuda_runtime.h>
#include <cstdint>

// ---------------------------------------------------------------------------
// RWKV-v4 forward, 6 layers. B=4, T=2048, H=A=1024, I=4096.
// Round 4: tf32 mma.sync tensor-core GEMMs (128x128x16, cp.async 2-stage),
//          cvt.rna.tf32 operand rounding; lambda removed (hardening).
// ---------------------------------------------------------------------------

#define Bz 4
#define Tt 2048
#define Hh 1024
#define Av 1024
#define Iv 4096
#define Lv 6
#define BT (Bz * Tt)                 // 8192 rows
#define SROW ((size_t)BT * Hh)       // 8388608 floats per [BT,H] buffer

// Scratch: h, x, xk, xv, xr, ry, k, v, r, y  (10 * SROW)  +  kk (BT*Iv)
__device__ float g_buf[10 * 8388608 + (size_t)BT * Iv];

// ---------------------------------------------------------------------------
// LayerNorm: one block per row, 256 threads, H=1024 (one float4 per thread)
// ---------------------------------------------------------------------------
__global__ __launch_bounds__(256) void ln_kernel(
    const float* __restrict__ in, float* __restrict__ out,
    const float* __restrict__ w, const float* __restrict__ b)
{
    const int n = blockIdx.x;
    const int tid = threadIdx.x;
    const float4 xv = ((const float4*)(in + (size_t)n * Hh))[tid];
    float s  = xv.x + xv.y + xv.z + xv.w;
    float sq = xv.x * xv.x + xv.y * xv.y + xv.z * xv.z + xv.w * xv.w;
#pragma unroll
    for (int o = 16; o; o >>= 1) {
        s  += __shfl_xor_sync(0xffffffffu, s,  o);
        sq += __shfl_xor_sync(0xffffffffu, sq, o);
    }
    __shared__ float ss[8], sqs[8];
    if ((tid & 31) == 0) { ss[tid >> 5] = s; sqs[tid >> 5] = sq; }
    __syncthreads();
    s = 0.f; sq = 0.f;
#pragma unroll
    for (int i = 0; i < 8; i++) { s += ss[i]; sq += sqs[i]; }
    const float mu  = s * (1.0f / Hh);
    const float var = sq * (1.0f / Hh) - mu * mu;
    const float rstd = rsqrtf(var + 1e-5f);
    const float4 w4 = ((const float4*)w)[tid];
    const float4 b4 = ((const float4*)b)[tid];
    float4 o4;
    o4.x = (xv.x - mu) * rstd * w4.x + b4.x;
    o4.y = (xv.y - mu) * rstd * w4.y + b4.y;
    o4.z = (xv.z - mu) * rstd * w4.z + b4.z;
    o4.w = (xv.w - mu) * rstd * w4.w + b4.w;
    ((float4*)(out + (size_t)n * Hh))[tid] = o4;
}

// Embedding gather + pre-LN fused
__global__ __launch_bounds__(256) void embed_ln_kernel(
    const int* __restrict__ ids, const float* __restrict__ embed,
    const float* __restrict__ w, const float* __restrict__ b,
    float* __restrict__ out)
{
    const int n = blockIdx.x;
    const int tid = threadIdx.x;
    const int id = ids[n];
    const float4 xv = ((const float4*)(embed + (size_t)id * Hh))[tid];
    float s  = xv.x + xv.y + xv.z + xv.w;
    float sq = xv.x * xv.x + xv.y * xv.y + xv.z * xv.z + xv.w * xv.w;
#pragma unroll
    for (int o = 16; o; o >>= 1) {
        s  += __shfl_xor_sync(0xffffffffu, s,  o);
        sq += __shfl_xor_sync(0xffffffffu, sq, o);
    }
    __shared__ float ss[8], sqs[8];
    if ((tid & 31) == 0) { ss[tid >> 5] = s; sqs[tid >> 5] = sq; }
    __syncthreads();
    s = 0.f; sq = 0.f;
#pragma unroll
    for (int i = 0; i < 8; i++) { s += ss[i]; sq += sqs[i]; }
    const float mu  = s * (1.0f / Hh);
    const float var = sq * (1.0f / Hh) - mu * mu;
    const float rstd = rsqrtf(var + 1e-5f);
    const float4 w4 = ((const float4*)w)[tid];
    const float4 b4 = ((const float4*)b)[tid];
    float4 o4;
    o4.x = (xv.x - mu) * rstd * w4.x + b4.x;
    o4.y = (xv.y - mu) * rstd * w4.y + b4.y;
    o4.z = (xv.z - mu) * rstd * w4.z + b4.z;
    o4.w = (xv.w - mu) * rstd * w4.w + b4.w;
    ((float4*)(out + (size_t)n * Hh))[tid] = o4;
}

// ---------------------------------------------------------------------------
// Token-shift mixing.
// ---------------------------------------------------------------------------
__global__ __launch_bounds__(256) void mix3_kernel(
    const float* __restrict__ x,
    const float* __restrict__ mk, const float* __restrict__ mv, const float* __restrict__ mr,
    float* __restrict__ xk, float* __restrict__ xv, float* __restrict__ xr)
{
    const int idx = blockIdx.x * 256 + threadIdx.x;   // float4 index
    const int n  = idx >> 8;
    const int j4 = idx & 255;
    const int t  = n & (Tt - 1);
    const float4 cur = ((const float4*)x)[idx];
    float4 prev = make_float4(0.f, 0.f, 0.f, 0.f);
    if (t > 0) prev = ((const float4*)x)[idx - 256];
    const float4 k4 = ((const float4*)mk)[j4];
    const float4 v4 = ((const float4*)mv)[j4];
    const float4 r4 = ((const float4*)mr)[j4];
    float4 o;
    o.x = prev.x + k4.x * (cur.x - prev.x); o.y = prev.y + k4.y * (cur.y - prev.y);
    o.z = prev.z + k4.z * (cur.z - prev.z); o.w = prev.w + k4.w * (cur.w - prev.w);
    ((float4*)xk)[idx] = o;
    o.x = prev.x + v4.x * (cur.x - prev.x); o.y = prev.y + v4.y * (cur.y - prev.y);
    o.z = prev.z + v4.z * (cur.z - prev.z); o.w = prev.w + v4.w * (cur.w - prev.w);
    ((float4*)xv)[idx] = o;
    o.x = prev.x + r4.x * (cur.x - prev.x); o.y = prev.y + r4.y * (cur.y - prev.y);
    o.z = prev.z + r4.z * (cur.z - prev.z); o.w = prev.w + r4.w * (cur.w - prev.w);
    ((float4*)xr)[idx] = o;
}

__global__ __launch_bounds__(256) void mix2_kernel(
    const float* __restrict__ x,
    const float* __restrict__ mk, const float* __restrict__ mr,
    float* __restrict__ xk, float* __restrict__ xr)
{
    const int idx = blockIdx.x * 256 + threadIdx.x;
    const int n  = idx >> 8;
    const int j4 = idx & 255;
    const int t  = n & (Tt - 1);
    const float4 cur = ((const float4*)x)[idx];
    float4 prev = make_float4(0.f, 0.f, 0.f, 0.f);
    if (t > 0) prev = ((const float4*)x)[idx - 256];
    const float4 k4 = ((const float4*)mk)[j4];
    const float4 r4 = ((const float4*)mr)[j4];
    float4 o;
    o.x = prev.x + k4.x * (cur.x - prev.x); o.y = prev.y + k4.y * (cur.y - prev.y);
    o.z = prev.z + k4.z * (cur.z - prev.z); o.w = prev.w + k4.w * (cur.w - prev.w);
    ((float4*)xk)[idx] = o;
    o.x = prev.x + r4.x * (cur.x - prev.x); o.y = prev.y + r4.y * (cur.y - prev.y);
    o.z = prev.z + r4.z * (cur.z - prev.z); o.w = prev.w + r4.w * (cur.w - prev.w);
    ((float4*)xr)[idx] = o;
}

// ---------------------------------------------------------------------------
// WKV recurrence: one thread per (batch, channel), sequential over T.
// ---------------------------------------------------------------------------
__global__ __launch_bounds__(128) void wkv_kernel(
    const float* __restrict__ k, const float* __restrict__ v,
    float* __restrict__ y,
    const float* __restrict__ tf, const float* __restrict__ td)
{
    const int idx = blockIdx.x * 128 + threadIdx.x;   // 0..4095
    const int b  = idx >> 10;
    const int ch = idx & (Av - 1);
    const float u = tf[ch];
    const float w = -__expf(td[ch]);
    const float* kp = k + (size_t)b * Tt * Av + ch;
    const float* vp = v + (size_t)b * Tt * Av + ch;
    float*       yp = y + (size_t)b * Tt * Av + ch;
    float aa = 0.f, bb = 0.f, p = -1e38f;
    for (int t = 0; t < Tt; t++) {
        const float kt = kp[(size_t)t * Av];
        const float vt = vp[(size_t)t * Av];
        const float uk = u + kt;
        const float q  = fmaxf(p, uk);
        const float e1 = __expf(p - q);
        const float e2 = __expf(uk - q);
        yp[(size_t)t * Av] = __fdividef(aa * e1 + e2 * vt, bb * e1 + e2);
        const float pw = p + w;
        const float q2 = fmaxf(pw, kt);
        const float s1 = __expf(pw - q2);
        const float s2 = __expf(kt - q2);
        aa = s1 * aa + s2 * vt;
        bb = s1 * bb + s2;
        p  = q2;
    }
}

__global__ __launch_bounds__(256) void rymul_kernel(
    const float* __restrict__ r, const float* __restrict__ y, float* __restrict__ ry)
{
    const int idx = blockIdx.x * 256 + threadIdx.x;
    const float4 a = ((const float4*)r)[idx];
    const float4 c = ((const float4*)y)[idx];
    float4 o;
    o.x = a.x * c.x; o.y = a.y * c.y; o.z = a.z * c.z; o.w = a.w * c.w;
    ((float4*)ry)[idx] = o;
}

// ---------------------------------------------------------------------------
// Tensor-core GEMM (tf32 mma.sync)
//   C[M,N] (op)= A[M,K] * B[N,K]^T      (NT, both K-major)
// Block: 128x128x16, 256 threads (8 warps, each 32x64).
// cp.async double-buffered smem; padded stride 20 => conflict-free LDS.
// EPI: 0 store, 1 sigmoid, 2 relu^2, 3 C+=acc, 4 C+=S*acc
// ---------------------------------------------------------------------------
#define GSTRIDE 20

__device__ __forceinline__ void mma_tf32(
    float& d0, float& d1, float& d2, float& d3,
    uint32_t a0, uint32_t a1, uint32_t a2, uint32_t a3,
    uint32_t b0, uint32_t b1)
{
    asm volatile(
        "mma.sync.aligned.m16n8k8.row.col.f32.tf32.tf32.f32 "
        "{%0,%1,%2,%3}, {%4,%5,%6,%7}, {%8,%9}, {%0,%1,%2,%3};\n"
        : "+f"(d0), "+f"(d1), "+f"(d2), "+f"(d3)
        : "r"(a0), "r"(a1), "r"(a2), "r"(a3), "r"(b0), "r"(b1));
}

__device__ __forceinline__ uint32_t f2tf32(float x)
{
    uint32_t r;
    asm("cvt.rna.tf32.f32 %0, %1;\n" : "=r"(r) : "f"(x));
    return r;
}

__device__ __forceinline__ void cp_async16(uint32_t smem, const void* gptr)
{
    asm volatile("cp.async.cg.shared.global [%0], [%1], 16;\n"
                 :: "r"(smem), "l"(gptr));
}

// Load one 128x16 A tile + 128x16 B tile into the given stage via cp.async.
__device__ __forceinline__ void gemm_load_tile(
    const float* Ag, const float* Bg, int K, int kt, int stage,
    int ldr0, int ldc, uint32_t smem_base)
{
    const uint32_t stage_bytes = 2u * 128u * GSTRIDE * 4u;
    const uint32_t opB_bytes   = 128u * GSTRIDE * 4u;
    const int kof = kt * 16 + ldc;
#pragma unroll
    for (int i = 0; i < 2; i++) {
        const int row = ldr0 + i * 64;
        uint32_t da = smem_base + stage * stage_bytes + (uint32_t)(row * GSTRIDE + ldc) * 4u;
        cp_async16(da, Ag + (size_t)row * K + kof);
        cp_async16(da + opB_bytes, Bg + (size_t)row * K + kof);
    }
    asm volatile("cp.async.commit_group;\n");
}

template <int EPI>
__global__ __launch_bounds__(256) void gemm_mma(
    const float* __restrict__ A, const float* __restrict__ B,
    float* __restrict__ C, const float* __restrict__ Sb,
    int M, int N, int K)
{
    __shared__ float sm[2][2][128 * GSTRIDE];

    const int tid  = threadIdx.x;
    const int lane = tid & 31;
    const int w    = tid >> 5;          // 0..7
    const int g    = lane >> 2;         // groupID 0..7
    const int tig  = lane & 3;          // thread-in-group
    const int mbase = (w >> 1) * 32;    // warp M offset (0,32,64,96)
    const int nbase = (w & 1) * 64;     // warp N offset (0,64)

    const float* Ag = A + (size_t)blockIdx.y * 128 * K;
    const float* Bg = B + (size_t)blockIdx.x * 128 * K;

    const int ldr0 = tid >> 2;          // row (0..63), +64 for 2nd
    const int ldc  = (tid & 3) * 4;     // float col within 16-wide k tile
    const uint32_t smem_base = (uint32_t)__cvta_generic_to_shared(&sm[0][0][0]);

    float acc[2][8][4];
#pragma unroll
    for (int mt = 0; mt < 2; mt++)
#pragma unroll
        for (int nt = 0; nt < 8; nt++)
#pragma unroll
            for (int e = 0; e < 4; e++) acc[mt][nt][e] = 0.f;

    const int KT = K >> 4;

    gemm_load_tile(Ag, Bg, K, 0, 0, ldr0, ldc, smem_base);

    for (int kt = 0; kt < KT; kt++) {
        if (kt + 1 < KT) {
            gemm_load_tile(Ag, Bg, K, kt + 1, (kt + 1) & 1, ldr0, ldc, smem_base);
            asm volatile("cp.async.wait_group 1;\n");
        } else {
            asm volatile("cp.async.wait_group 0;\n");
        }
        __syncthreads();

        const float* As = sm[kt & 1][0];
        const float* Bs = sm[kt & 1][1];
#pragma unroll
        for (int ks = 0; ks < 2; ks++) {
            const int kb = ks * 8;
            uint32_t af[2][4], bf[8][2];
#pragma unroll
            for (int mt = 0; mt < 2; mt++) {
                const int r = mbase + mt * 16 + g;
                af[mt][0] = f2tf32(As[r * GSTRIDE + kb + tig]);
                af[mt][1] = f2tf32(As[(r + 8) * GSTRIDE + kb + tig]);
                af[mt][2] = f2tf32(As[r * GSTRIDE + kb + tig + 4]);
                af[mt][3] = f2tf32(As[(r + 8) * GSTRIDE + kb + tig + 4]);
            }
#pragma unroll
            for (int nt = 0; nt < 8; nt++) {
                const int c = nbase + nt * 8 + g;
                bf[nt][0] = f2tf32(Bs[c * GSTRIDE + kb + tig]);
                bf[nt][1] = f2tf32(Bs[c * GSTRIDE + kb + tig + 4]);
            }
#pragma unroll
            for (int mt = 0; mt < 2; mt++)
#pragma unroll
                for (int nt = 0; nt < 8; nt++)
                    mma_tf32(acc[mt][nt][0], acc[mt][nt][1], acc[mt][nt][2], acc[mt][nt][3],
                             af[mt][0], af[mt][1], af[mt][2], af[mt][3],
                             bf[nt][0], bf[nt][1]);
        }
        __syncthreads();
    }

    // ---- epilogue ----
#pragma unroll
    for (int mt = 0; mt < 2; mt++) {
        const size_t row0 = (size_t)blockIdx.y * 128 + mbase + mt * 16 + g;
#pragma unroll
        for (int nt = 0; nt < 8; nt++) {
            const size_t col = (size_t)blockIdx.x * 128 + nbase + nt * 8 + 2 * tig;
#pragma unroll
            for (int half = 0; half < 2; half++) {
                const size_t r = row0 + half * 8;
                float v0 = acc[mt][nt][half * 2 + 0];
                float v1 = acc[mt][nt][half * 2 + 1];
                float* cp = C + r * N + col;
                if (EPI == 0) {
                    cp[0] = v0; cp[1] = v1;
                } else if (EPI == 1) {
                    cp[0] = 1.f / (1.f + __expf(-v0));
                    cp[1] = 1.f / (1.f + __expf(-v1));
                } else if (EPI == 2) {
                    float t0 = fmaxf(v0, 0.f), t1 = fmaxf(v1, 0.f);
                    cp[0] = t0 * t0; cp[1] = t1 * t1;
                } else if (EPI == 3) {
                    cp[0] += v0; cp[1] += v1;
                } else {
                    const float* sp = Sb + r * N + col;
                    cp[0] += sp[0] * v0; cp[1] += sp[1] * v1;
                }
            }
        }
    }
}

// ---------------------------------------------------------------------------
// Host launcher
// ---------------------------------------------------------------------------
extern "C" void kernel_launch(void* const* d_in, const int* in_sizes, int n_in,
                              void* d_out, int out_size)
{
    const int*   ids    = (const int*)  d_in[0];
    const float* embed  = (const float*)d_in[1];
    const float* pre_w  = (const float*)d_in[2];
    const float* pre_b  = (const float*)d_in[3];
    const float* post_w = (const float*)d_in[4];
    const float* post_b = (const float*)d_in[5];
    const float* ln1_w  = (const float*)d_in[6];
    const float* ln1_b  = (const float*)d_in[7];
    const float* ln2_w  = (const float*)d_in[8];
    const float* ln2_b  = (const float*)d_in[9];
    const float* amk    = (const float*)d_in[10];
    const float* amv    = (const float*)d_in[11];
    const float* amr    = (const float*)d_in[12];
    const float* awk    = (const float*)d_in[13];
    const float* awv    = (const float*)d_in[14];
    const float* awr    = (const float*)d_in[15];
    const float* awo    = (const float*)d_in[16];
    const float* tdec   = (const float*)d_in[17];
    const float* tfirst = (const float*)d_in[18];
    const float* fmk    = (const float*)d_in[19];
    const float* fmr    = (const float*)d_in[20];
    const float* fwk    = (const float*)d_in[21];
    const float* fwr    = (const float*)d_in[22];
    const float* fwv    = (const float*)d_in[23];

    float* base = nullptr;
    cudaGetSymbolAddress((void**)&base, g_buf);
    float* h   = base;
    float* x   = base + 1 * SROW;
    float* xk  = base + 2 * SROW;
    float* xv  = base + 3 * SROW;
    float* xr  = base + 4 * SROW;
    float* ry  = base + 5 * SROW;
    float* kb  = base + 6 * SROW;
    float* vb  = base + 7 * SROW;
    float* rb  = base + 8 * SROW;
    float* yb  = base + 9 * SROW;
    float* kkb = base + 10 * SROW;

    const int EW_BLOCKS = (BT * Hh / 4) / 256;   // 8192
    const dim3 gA(Av / 128, BT / 128);
    const dim3 gH(Hh / 128, BT / 128);
    const dim3 gI(Iv / 128, BT / 128);

    embed_ln_kernel<<<BT, 256>>>(ids, embed, pre_w, pre_b, h);

    for (int i = 0; i < Lv; i++) {
        // --- attention (time mixing) ---
        ln_kernel<<<BT, 256>>>(h, x, ln1_w + i * Hh, ln1_b + i * Hh);
        mix3_kernel<<<EW_BLOCKS, 256>>>(x, amk + i * Hh, amv + i * Hh, amr + i * Hh,
                                        xk, xv, xr);
        gemm_mma<0><<<gA, 256>>>(xk, awk + (size_t)i * Av * Hh, kb, nullptr, BT, Av, Hh);
        gemm_mma<0><<<gA, 256>>>(xv, awv + (size_t)i * Av * Hh, vb, nullptr, BT, Av, Hh);
        gemm_mma<1><<<gA, 256>>>(xr, awr + (size_t)i * Av * Hh, rb, nullptr, BT, Av, Hh);
        wkv_kernel<<<32, 128>>>(kb, vb, yb, tfirst + i * Av, tdec + i * Av);
        rymul_kernel<<<EW_BLOCKS, 256>>>(rb, yb, ry);
        gemm_mma<3><<<gH, 256>>>(ry, awo + (size_t)i * Hh * Av, h, nullptr, BT, Hh, Av);

        // --- feed forward (channel mixing) ---
        ln_kernel<<<BT, 256>>>(h, x, ln2_w + i * Hh, ln2_b + i * Hh);
        mix2_kernel<<<EW_BLOCKS, 256>>>(x, fmk + i * Hh, fmr + i * Hh, xk, xr);
        gemm_mma<2><<<gI, 256>>>(xk, fwk + (size_t)i * Iv * Hh, kkb, nullptr, BT, Iv, Hh);
        gemm_mma<1><<<gH, 256>>>(xr, fwr + (size_t)i * Hh * Hh, rb, nullptr, BT, Hh, Hh);
        gemm_mma<4><<<gH, 256>>>(kkb, fwv + (size_t)i * Hh * Iv, h, rb, BT, Hh, Iv);
    }

    ln_kernel<<<BT, 256>>>(h, (float*)d_out, post_w, post_b);
}

// round 9
// speedup vs baseline: 2.6481x; 1.0385x over previous
#include <cuda_runtime.h>
#include <cstdint>

// ---------------------------------------------------------------------------
// RWKV-v4 forward, 6 layers. B=4, T=2048, H=A=1024, I=4096.
// Round 9: tf32 mma.sync GEMMs; cvt hoisted out of inner loop (weights
// pre-rounded to tf32 in scratch, activations rounded at producers);
// fused k/v/r GEMM triple; WKV spread over 128 SMs.
// ---------------------------------------------------------------------------

#define Bz 4
#define Tt 2048
#define Hh 1024
#define Av 1024
#define Iv 4096
#define Lv 6
#define BT (Bz * Tt)                 // 8192 rows
#define SROW ((size_t)BT * Hh)       // 8388608 floats per [BT,H] buffer

// activation scratch (10*SROW) + kk (BT*Iv) + rounded weights (81,788,928)
#define WOFF ((size_t)10 * 8388608 + (size_t)BT * Iv)
__device__ float g_buf[WOFF + 81788928];

__device__ __forceinline__ uint32_t f2tf32(float x)
{
    uint32_t r;
    asm("cvt.rna.tf32.f32 %0, %1;\n" : "=r"(r) : "f"(x));
    return r;
}
__device__ __forceinline__ float round_tf32(float x)
{
    return __uint_as_float(f2tf32(x));
}

// ---------------------------------------------------------------------------
// Weight pre-rounding: out[i] = tf32_rna(in[i]).  n4 = count/4, exact blocks.
// ---------------------------------------------------------------------------
__global__ __launch_bounds__(256) void round4_kernel(
    const float4* __restrict__ in, float4* __restrict__ out)
{
    const int idx = blockIdx.x * 256 + threadIdx.x;
    float4 v = in[idx];
    v.x = round_tf32(v.x); v.y = round_tf32(v.y);
    v.z = round_tf32(v.z); v.w = round_tf32(v.w);
    out[idx] = v;
}

// ---------------------------------------------------------------------------
// LayerNorm: one block per row, 256 threads, H=1024
// ---------------------------------------------------------------------------
__global__ __launch_bounds__(256) void ln_kernel(
    const float* __restrict__ in, float* __restrict__ out,
    const float* __restrict__ w, const float* __restrict__ b)
{
    const int n = blockIdx.x;
    const int tid = threadIdx.x;
    const float4 xv = ((const float4*)(in + (size_t)n * Hh))[tid];
    float s  = xv.x + xv.y + xv.z + xv.w;
    float sq = xv.x * xv.x + xv.y * xv.y + xv.z * xv.z + xv.w * xv.w;
#pragma unroll
    for (int o = 16; o; o >>= 1) {
        s  += __shfl_xor_sync(0xffffffffu, s,  o);
        sq += __shfl_xor_sync(0xffffffffu, sq, o);
    }
    __shared__ float ss[8], sqs[8];
    if ((tid & 31) == 0) { ss[tid >> 5] = s; sqs[tid >> 5] = sq; }
    __syncthreads();
    s = 0.f; sq = 0.f;
#pragma unroll
    for (int i = 0; i < 8; i++) { s += ss[i]; sq += sqs[i]; }
    const float mu  = s * (1.0f / Hh);
    const float var = sq * (1.0f / Hh) - mu * mu;
    const float rstd = rsqrtf(var + 1e-5f);
    const float4 w4 = ((const float4*)w)[tid];
    const float4 b4 = ((const float4*)b)[tid];
    float4 o4;
    o4.x = (xv.x - mu) * rstd * w4.x + b4.x;
    o4.y = (xv.y - mu) * rstd * w4.y + b4.y;
    o4.z = (xv.z - mu) * rstd * w4.z + b4.z;
    o4.w = (xv.w - mu) * rstd * w4.w + b4.w;
    ((float4*)(out + (size_t)n * Hh))[tid] = o4;
}

__global__ __launch_bounds__(256) void embed_ln_kernel(
    const int* __restrict__ ids, const float* __restrict__ embed,
    const float* __restrict__ w, const float* __restrict__ b,
    float* __restrict__ out)
{
    const int n = blockIdx.x;
    const int tid = threadIdx.x;
    const int id = ids[n];
    const float4 xv = ((const float4*)(embed + (size_t)id * Hh))[tid];
    float s  = xv.x + xv.y + xv.z + xv.w;
    float sq = xv.x * xv.x + xv.y * xv.y + xv.z * xv.z + xv.w * xv.w;
#pragma unroll
    for (int o = 16; o; o >>= 1) {
        s  += __shfl_xor_sync(0xffffffffu, s,  o);
        sq += __shfl_xor_sync(0xffffffffu, sq, o);
    }
    __shared__ float ss[8], sqs[8];
    if ((tid & 31) == 0) { ss[tid >> 5] = s; sqs[tid >> 5] = sq; }
    __syncthreads();
    s = 0.f; sq = 0.f;
#pragma unroll
    for (int i = 0; i < 8; i++) { s += ss[i]; sq += sqs[i]; }
    const float mu  = s * (1.0f / Hh);
    const float var = sq * (1.0f / Hh) - mu * mu;
    const float rstd = rsqrtf(var + 1e-5f);
    const float4 w4 = ((const float4*)w)[tid];
    const float4 b4 = ((const float4*)b)[tid];
    float4 o4;
    o4.x = (xv.x - mu) * rstd * w4.x + b4.x;
    o4.y = (xv.y - mu) * rstd * w4.y + b4.y;
    o4.z = (xv.z - mu) * rstd * w4.z + b4.z;
    o4.w = (xv.w - mu) * rstd * w4.w + b4.w;
    ((float4*)(out + (size_t)n * Hh))[tid] = o4;
}

// ---------------------------------------------------------------------------
// Token-shift mixing. Outputs rounded to tf32 (GEMM A operands).
// ---------------------------------------------------------------------------
__global__ __launch_bounds__(256) void mix3_kernel(
    const float* __restrict__ x,
    const float* __restrict__ mk, const float* __restrict__ mv, const float* __restrict__ mr,
    float* __restrict__ xk, float* __restrict__ xv, float* __restrict__ xr)
{
    const int idx = blockIdx.x * 256 + threadIdx.x;   // float4 index
    const int n  = idx >> 8;
    const int j4 = idx & 255;
    const int t  = n & (Tt - 1);
    const float4 cur = ((const float4*)x)[idx];
    float4 prev = make_float4(0.f, 0.f, 0.f, 0.f);
    if (t > 0) prev = ((const float4*)x)[idx - 256];
    const float4 k4 = ((const float4*)mk)[j4];
    const float4 v4 = ((const float4*)mv)[j4];
    const float4 r4 = ((const float4*)mr)[j4];
    float4 o;
    o.x = round_tf32(prev.x + k4.x * (cur.x - prev.x));
    o.y = round_tf32(prev.y + k4.y * (cur.y - prev.y));
    o.z = round_tf32(prev.z + k4.z * (cur.z - prev.z));
    o.w = round_tf32(prev.w + k4.w * (cur.w - prev.w));
    ((float4*)xk)[idx] = o;
    o.x = round_tf32(prev.x + v4.x * (cur.x - prev.x));
    o.y = round_tf32(prev.y + v4.y * (cur.y - prev.y));
    o.z = round_tf32(prev.z + v4.z * (cur.z - prev.z));
    o.w = round_tf32(prev.w + v4.w * (cur.w - prev.w));
    ((float4*)xv)[idx] = o;
    o.x = round_tf32(prev.x + r4.x * (cur.x - prev.x));
    o.y = round_tf32(prev.y + r4.y * (cur.y - prev.y));
    o.z = round_tf32(prev.z + r4.z * (cur.z - prev.z));
    o.w = round_tf32(prev.w + r4.w * (cur.w - prev.w));
    ((float4*)xr)[idx] = o;
}

__global__ __launch_bounds__(256) void mix2_kernel(
    const float* __restrict__ x,
    const float* __restrict__ mk, const float* __restrict__ mr,
    float* __restrict__ xk, float* __restrict__ xr)
{
    const int idx = blockIdx.x * 256 + threadIdx.x;
    const int n  = idx >> 8;
    const int j4 = idx & 255;
    const int t  = n & (Tt - 1);
    const float4 cur = ((const float4*)x)[idx];
    float4 prev = make_float4(0.f, 0.f, 0.f, 0.f);
    if (t > 0) prev = ((const float4*)x)[idx - 256];
    const float4 k4 = ((const float4*)mk)[j4];
    const float4 r4 = ((const float4*)mr)[j4];
    float4 o;
    o.x = round_tf32(prev.x + k4.x * (cur.x - prev.x));
    o.y = round_tf32(prev.y + k4.y * (cur.y - prev.y));
    o.z = round_tf32(prev.z + k4.z * (cur.z - prev.z));
    o.w = round_tf32(prev.w + k4.w * (cur.w - prev.w));
    ((float4*)xk)[idx] = o;
    o.x = round_tf32(prev.x + r4.x * (cur.x - prev.x));
    o.y = round_tf32(prev.y + r4.y * (cur.y - prev.y));
    o.z = round_tf32(prev.z + r4.z * (cur.z - prev.z));
    o.w = round_tf32(prev.w + r4.w * (cur.w - prev.w));
    ((float4*)xr)[idx] = o;
}

// ---------------------------------------------------------------------------
// WKV recurrence: one thread per (batch, channel); 128 blocks x 32 threads.
// ---------------------------------------------------------------------------
__global__ __launch_bounds__(32) void wkv_kernel(
    const float* __restrict__ k, const float* __restrict__ v,
    float* __restrict__ y,
    const float* __restrict__ tf, const float* __restrict__ td)
{
    const int idx = blockIdx.x * 32 + threadIdx.x;    // 0..4095
    const int b  = idx >> 10;
    const int ch = idx & (Av - 1);
    const float u = tf[ch];
    const float w = -__expf(td[ch]);
    const float* kp = k + (size_t)b * Tt * Av + ch;
    const float* vp = v + (size_t)b * Tt * Av + ch;
    float*       yp = y + (size_t)b * Tt * Av + ch;
    float aa = 0.f, bb = 0.f, p = -1e38f;
#pragma unroll 4
    for (int t = 0; t < Tt; t++) {
        const float kt = kp[(size_t)t * Av];
        const float vt = vp[(size_t)t * Av];
        const float uk = u + kt;
        const float q  = fmaxf(p, uk);
        const float e1 = __expf(p - q);
        const float e2 = __expf(uk - q);
        yp[(size_t)t * Av] = __fdividef(aa * e1 + e2 * vt, bb * e1 + e2);
        const float pw = p + w;
        const float q2 = fmaxf(pw, kt);
        const float s1 = __expf(pw - q2);
        const float s2 = __expf(kt - q2);
        aa = s1 * aa + s2 * vt;
        bb = s1 * bb + s2;
        p  = q2;
    }
}

// ry = r * y, rounded (GEMM A operand)
__global__ __launch_bounds__(256) void rymul_kernel(
    const float* __restrict__ r, const float* __restrict__ y, float* __restrict__ ry)
{
    const int idx = blockIdx.x * 256 + threadIdx.x;
    const float4 a = ((const float4*)r)[idx];
    const float4 c = ((const float4*)y)[idx];
    float4 o;
    o.x = round_tf32(a.x * c.x); o.y = round_tf32(a.y * c.y);
    o.z = round_tf32(a.z * c.z); o.w = round_tf32(a.w * c.w);
    ((float4*)ry)[idx] = o;
}

// ---------------------------------------------------------------------------
// Tensor-core GEMM (tf32 mma.sync), operands pre-rounded in gmem.
//   C[M,N] (op)= A[M,K] * B[N,K]^T
// Block 128x128x16, 256 threads (8 warps @ 32x64), cp.async 2-stage.
// EPI: 0 store, 1 sigmoid, 2 relu^2 (rounded), 3 C+=acc, 4 C+=S*acc
// ---------------------------------------------------------------------------
#define GSTRIDE 20

__device__ __forceinline__ void mma_tf32(
    float& d0, float& d1, float& d2, float& d3,
    uint32_t a0, uint32_t a1, uint32_t a2, uint32_t a3,
    uint32_t b0, uint32_t b1)
{
    asm volatile(
        "mma.sync.aligned.m16n8k8.row.col.f32.tf32.tf32.f32 "
        "{%0,%1,%2,%3}, {%4,%5,%6,%7}, {%8,%9}, {%0,%1,%2,%3};\n"
        : "+f"(d0), "+f"(d1), "+f"(d2), "+f"(d3)
        : "r"(a0), "r"(a1), "r"(a2), "r"(a3), "r"(b0), "r"(b1));
}

__device__ __forceinline__ void cp_async16(uint32_t smem, const void* gptr)
{
    asm volatile("cp.async.cg.shared.global [%0], [%1], 16;\n"
                 :: "r"(smem), "l"(gptr));
}

__device__ __forceinline__ void gemm_load_tile(
    const float* Ag, const float* Bg, int K, int kt, int stage,
    int ldr0, int ldc, uint32_t smem_base)
{
    const uint32_t stage_bytes = 2u * 128u * GSTRIDE * 4u;
    const uint32_t opB_bytes   = 128u * GSTRIDE * 4u;
    const int kof = kt * 16 + ldc;
#pragma unroll
    for (int i = 0; i < 2; i++) {
        const int row = ldr0 + i * 64;
        uint32_t da = smem_base + stage * stage_bytes + (uint32_t)(row * GSTRIDE + ldc) * 4u;
        cp_async16(da, Ag + (size_t)row * K + kof);
        cp_async16(da + opB_bytes, Bg + (size_t)row * K + kof);
    }
    asm volatile("cp.async.commit_group;\n");
}

// Core compute shared by both GEMM entry points.
// sig_epi selects at runtime inside epilogue only when EPI==5 (triple kernel).
template <int EPI>
__device__ __forceinline__ void gemm_body(
    const float* Ag, const float* Bg, float* C, const float* Sb,
    int N, int K, int bx, int by, bool sig)
{
    __shared__ float sm[2][2][128 * GSTRIDE];

    const int tid  = threadIdx.x;
    const int lane = tid & 31;
    const int w    = tid >> 5;
    const int g    = lane >> 2;
    const int tig  = lane & 3;
    const int mbase = (w >> 1) * 32;
    const int nbase = (w & 1) * 64;

    const int ldr0 = tid >> 2;
    const int ldc  = (tid & 3) * 4;
    const uint32_t smem_base = (uint32_t)__cvta_generic_to_shared(&sm[0][0][0]);

    float acc[2][8][4];
#pragma unroll
    for (int mt = 0; mt < 2; mt++)
#pragma unroll
        for (int nt = 0; nt < 8; nt++)
#pragma unroll
            for (int e = 0; e < 4; e++) acc[mt][nt][e] = 0.f;

    const int KT = K >> 4;

    gemm_load_tile(Ag, Bg, K, 0, 0, ldr0, ldc, smem_base);

    for (int kt = 0; kt < KT; kt++) {
        if (kt + 1 < KT) {
            gemm_load_tile(Ag, Bg, K, kt + 1, (kt + 1) & 1, ldr0, ldc, smem_base);
            asm volatile("cp.async.wait_group 1;\n");
        } else {
            asm volatile("cp.async.wait_group 0;\n");
        }
        __syncthreads();

        const float* As = sm[kt & 1][0];
        const float* Bs = sm[kt & 1][1];
#pragma unroll
        for (int ks = 0; ks < 2; ks++) {
            const int kb = ks * 8;
            uint32_t af[2][4], bf[8][2];
#pragma unroll
            for (int mt = 0; mt < 2; mt++) {
                const int r = mbase + mt * 16 + g;
                af[mt][0] = __float_as_uint(As[r * GSTRIDE + kb + tig]);
                af[mt][1] = __float_as_uint(As[(r + 8) * GSTRIDE + kb + tig]);
                af[mt][2] = __float_as_uint(As[r * GSTRIDE + kb + tig + 4]);
                af[mt][3] = __float_as_uint(As[(r + 8) * GSTRIDE + kb + tig + 4]);
            }
#pragma unroll
            for (int nt = 0; nt < 8; nt++) {
                const int c = nbase + nt * 8 + g;
                bf[nt][0] = __float_as_uint(Bs[c * GSTRIDE + kb + tig]);
                bf[nt][1] = __float_as_uint(Bs[c * GSTRIDE + kb + tig + 4]);
            }
#pragma unroll
            for (int mt = 0; mt < 2; mt++)
#pragma unroll
                for (int nt = 0; nt < 8; nt++)
                    mma_tf32(acc[mt][nt][0], acc[mt][nt][1], acc[mt][nt][2], acc[mt][nt][3],
                             af[mt][0], af[mt][1], af[mt][2], af[mt][3],
                             bf[nt][0], bf[nt][1]);
        }
        __syncthreads();
    }

#pragma unroll
    for (int mt = 0; mt < 2; mt++) {
        const size_t row0 = (size_t)by * 128 + mbase + mt * 16 + g;
#pragma unroll
        for (int nt = 0; nt < 8; nt++) {
            const size_t col = (size_t)bx * 128 + nbase + nt * 8 + 2 * tig;
#pragma unroll
            for (int half = 0; half < 2; half++) {
                const size_t r = row0 + half * 8;
                float v0 = acc[mt][nt][half * 2 + 0];
                float v1 = acc[mt][nt][half * 2 + 1];
                float* cp = C + r * N + col;
                if (EPI == 0) {
                    cp[0] = v0; cp[1] = v1;
                } else if (EPI == 1) {
                    cp[0] = 1.f / (1.f + __expf(-v0));
                    cp[1] = 1.f / (1.f + __expf(-v1));
                } else if (EPI == 2) {
                    float t0 = fmaxf(v0, 0.f), t1 = fmaxf(v1, 0.f);
                    cp[0] = round_tf32(t0 * t0); cp[1] = round_tf32(t1 * t1);
                } else if (EPI == 3) {
                    cp[0] += v0; cp[1] += v1;
                } else if (EPI == 4) {
                    const float* sp = Sb + r * N + col;
                    cp[0] += sp[0] * v0; cp[1] += sp[1] * v1;
                } else { // EPI == 5: runtime store/sigmoid select
                    if (sig) {
                        cp[0] = 1.f / (1.f + __expf(-v0));
                        cp[1] = 1.f / (1.f + __expf(-v1));
                    } else {
                        cp[0] = v0; cp[1] = v1;
                    }
                }
            }
        }
    }
}

template <int EPI>
__global__ __launch_bounds__(256) void gemm_mma(
    const float* __restrict__ A, const float* __restrict__ B,
    float* __restrict__ C, const float* __restrict__ Sb,
    int M, int N, int K)
{
    gemm_body<EPI>(A + (size_t)blockIdx.y * 128 * K,
                   B + (size_t)blockIdx.x * 128 * K,
                   C, Sb, N, K, blockIdx.x, blockIdx.y, false);
}

// Fused k/v/r projection triple: z selects (A,B,C); z==2 applies sigmoid.
__global__ __launch_bounds__(256) void gemm3_mma(
    const float* __restrict__ A0, const float* __restrict__ B0, float* __restrict__ C0,
    const float* __restrict__ A1, const float* __restrict__ B1, float* __restrict__ C1,
    const float* __restrict__ A2, const float* __restrict__ B2, float* __restrict__ C2,
    int N, int K)
{
    const int z = blockIdx.z;
    const float* A; const float* B; float* C;
    if (z == 0)      { A = A0; B = B0; C = C0; }
    else if (z == 1) { A = A1; B = B1; C = C1; }
    else             { A = A2; B = B2; C = C2; }
    gemm_body<5>(A + (size_t)blockIdx.y * 128 * K,
                 B + (size_t)blockIdx.x * 128 * K,
                 C, nullptr, N, K, blockIdx.x, blockIdx.y, z == 2);
}

// ---------------------------------------------------------------------------
// Host launcher
// ---------------------------------------------------------------------------
extern "C" void kernel_launch(void* const* d_in, const int* in_sizes, int n_in,
                              void* d_out, int out_size)
{
    const int*   ids    = (const int*)  d_in[0];
    const float* embed  = (const float*)d_in[1];
    const float* pre_w  = (const float*)d_in[2];
    const float* pre_b  = (const float*)d_in[3];
    const float* post_w = (const float*)d_in[4];
    const float* post_b = (const float*)d_in[5];
    const float* ln1_w  = (const float*)d_in[6];
    const float* ln1_b  = (const float*)d_in[7];
    const float* ln2_w  = (const float*)d_in[8];
    const float* ln2_b  = (const float*)d_in[9];
    const float* amk    = (const float*)d_in[10];
    const float* amv    = (const float*)d_in[11];
    const float* amr    = (const float*)d_in[12];
    const float* awk    = (const float*)d_in[13];
    const float* awv    = (const float*)d_in[14];
    const float* awr    = (const float*)d_in[15];
    const float* awo    = (const float*)d_in[16];
    const float* tdec   = (const float*)d_in[17];
    const float* tfirst = (const float*)d_in[18];
    const float* fmk    = (const float*)d_in[19];
    const float* fmr    = (const float*)d_in[20];
    const float* fwk    = (const float*)d_in[21];
    const float* fwr    = (const float*)d_in[22];
    const float* fwv    = (const float*)d_in[23];

    float* base = nullptr;
    cudaGetSymbolAddress((void**)&base, g_buf);
    float* h   = base;
    float* x   = base + 1 * SROW;
    float* xk  = base + 2 * SROW;
    float* xv  = base + 3 * SROW;
    float* xr  = base + 4 * SROW;
    float* ry  = base + 5 * SROW;
    float* kb  = base + 6 * SROW;
    float* vb  = base + 7 * SROW;
    float* rb  = base + 8 * SROW;
    float* yb  = base + 9 * SROW;
    float* kkb = base + 10 * SROW;

    // rounded weight copies
    const size_t nAH = (size_t)Lv * Av * Hh;   // 6,291,456
    const size_t nIH = (size_t)Lv * Iv * Hh;   // 25,165,824
    float* wawk = base + WOFF;
    float* wawv = wawk + nAH;
    float* wawr = wawv + nAH;
    float* wawo = wawr + nAH;
    float* wfwk = wawo + nAH;
    float* wfwr = wfwk + nIH;
    float* wfwv = wfwr + nAH;

    round4_kernel<<<(int)(nAH / 1024), 256>>>((const float4*)awk, (float4*)wawk);
    round4_kernel<<<(int)(nAH / 1024), 256>>>((const float4*)awv, (float4*)wawv);
    round4_kernel<<<(int)(nAH / 1024), 256>>>((const float4*)awr, (float4*)wawr);
    round4_kernel<<<(int)(nAH / 1024), 256>>>((const float4*)awo, (float4*)wawo);
    round4_kernel<<<(int)(nIH / 1024), 256>>>((const float4*)fwk, (float4*)wfwk);
    round4_kernel<<<(int)(nAH / 1024), 256>>>((const float4*)fwr, (float4*)wfwr);
    round4_kernel<<<(int)(nIH / 1024), 256>>>((const float4*)fwv, (float4*)wfwv);

    const int EW_BLOCKS = (BT * Hh / 4) / 256;   // 8192
    const dim3 gA3(Av / 128, BT / 128, 3);
    const dim3 gH(Hh / 128, BT / 128);
    const dim3 gI(Iv / 128, BT / 128);

    embed_ln_kernel<<<BT, 256>>>(ids, embed, pre_w, pre_b, h);

    for (int i = 0; i < Lv; i++) {
        // --- attention (time mixing) ---
        ln_kernel<<<BT, 256>>>(h, x, ln1_w + i * Hh, ln1_b + i * Hh);
        mix3_kernel<<<EW_BLOCKS, 256>>>(x, amk + i * Hh, amv + i * Hh, amr + i * Hh,
                                        xk, xv, xr);
        gemm3_mma<<<gA3, 256>>>(xk, wawk + (size_t)i * Av * Hh, kb,
                                xv, wawv + (size_t)i * Av * Hh, vb,
                                xr, wawr + (size_t)i * Av * Hh, rb,
                                Av, Hh);
        wkv_kernel<<<128, 32>>>(kb, vb, yb, tfirst + i * Av, tdec + i * Av);
        rymul_kernel<<<EW_BLOCKS, 256>>>(rb, yb, ry);
        gemm_mma<3><<<gH, 256>>>(ry, wawo + (size_t)i * Hh * Av, h, nullptr, BT, Hh, Av);

        // --- feed forward (channel mixing) ---
        ln_kernel<<<BT, 256>>>(h, x, ln2_w + i * Hh, ln2_b + i * Hh);
        mix2_kernel<<<EW_BLOCKS, 256>>>(x, fmk + i * Hh, fmr + i * Hh, xk, xr);
        gemm_mma<2><<<gI, 256>>>(xk, wfwk + (size_t)i * Iv * Hh, kkb, nullptr, BT, Iv, Hh);
        gemm_mma<1><<<gH, 256>>>(xr, wfwr + (size_t)i * Hh * Hh, rb, nullptr, BT, Hh, Hh);
        gemm_mma<4><<<gH, 256>>>(kkb, wfwv + (size_t)i * Hh * Iv, h, rb, BT, Hh, Iv);
    }

    ln_kernel<<<BT, 256>>>(h, (float*)d_out, post_w, post_b);
}

// round 14
// speedup vs baseline: 2.7739x; 1.0475x over previous
#include <cuda_runtime.h>
#include <cstdint>

// ---------------------------------------------------------------------------
// RWKV-v4 forward, 6 layers. B=4, T=2048, H=A=1024, I=4096.
// Round 10: tf32 mma.sync GEMMs with 64x64 warp tiles (4 warps / CTA,
// 1.0 LDS per MMA); pre-rounded weights; fused k/v/r triple; WKV on 128 SMs.
// ---------------------------------------------------------------------------

#define Bz 4
#define Tt 2048
#define Hh 1024
#define Av 1024
#define Iv 4096
#define Lv 6
#define BT (Bz * Tt)                 // 8192 rows
#define SROW ((size_t)BT * Hh)       // 8388608 floats per [BT,H] buffer

// activation scratch (10*SROW) + kk (BT*Iv) + rounded weights (81,788,928)
#define WOFF ((size_t)10 * 8388608 + (size_t)BT * Iv)
__device__ float g_buf[WOFF + 81788928];

__device__ __forceinline__ uint32_t f2tf32(float x)
{
    uint32_t r;
    asm("cvt.rna.tf32.f32 %0, %1;\n" : "=r"(r) : "f"(x));
    return r;
}
__device__ __forceinline__ float round_tf32(float x)
{
    return __uint_as_float(f2tf32(x));
}

// ---------------------------------------------------------------------------
// Weight pre-rounding: out[i] = tf32_rna(in[i]).
// ---------------------------------------------------------------------------
__global__ __launch_bounds__(256) void round4_kernel(
    const float4* __restrict__ in, float4* __restrict__ out)
{
    const int idx = blockIdx.x * 256 + threadIdx.x;
    float4 v = in[idx];
    v.x = round_tf32(v.x); v.y = round_tf32(v.y);
    v.z = round_tf32(v.z); v.w = round_tf32(v.w);
    out[idx] = v;
}

// ---------------------------------------------------------------------------
// LayerNorm: one block per row, 256 threads, H=1024
// ---------------------------------------------------------------------------
__global__ __launch_bounds__(256) void ln_kernel(
    const float* __restrict__ in, float* __restrict__ out,
    const float* __restrict__ w, const float* __restrict__ b)
{
    const int n = blockIdx.x;
    const int tid = threadIdx.x;
    const float4 xv = ((const float4*)(in + (size_t)n * Hh))[tid];
    float s  = xv.x + xv.y + xv.z + xv.w;
    float sq = xv.x * xv.x + xv.y * xv.y + xv.z * xv.z + xv.w * xv.w;
#pragma unroll
    for (int o = 16; o; o >>= 1) {
        s  += __shfl_xor_sync(0xffffffffu, s,  o);
        sq += __shfl_xor_sync(0xffffffffu, sq, o);
    }
    __shared__ float ss[8], sqs[8];
    if ((tid & 31) == 0) { ss[tid >> 5] = s; sqs[tid >> 5] = sq; }
    __syncthreads();
    s = 0.f; sq = 0.f;
#pragma unroll
    for (int i = 0; i < 8; i++) { s += ss[i]; sq += sqs[i]; }
    const float mu  = s * (1.0f / Hh);
    const float var = sq * (1.0f / Hh) - mu * mu;
    const float rstd = rsqrtf(var + 1e-5f);
    const float4 w4 = ((const float4*)w)[tid];
    const float4 b4 = ((const float4*)b)[tid];
    float4 o4;
    o4.x = (xv.x - mu) * rstd * w4.x + b4.x;
    o4.y = (xv.y - mu) * rstd * w4.y + b4.y;
    o4.z = (xv.z - mu) * rstd * w4.z + b4.z;
    o4.w = (xv.w - mu) * rstd * w4.w + b4.w;
    ((float4*)(out + (size_t)n * Hh))[tid] = o4;
}

__global__ __launch_bounds__(256) void embed_ln_kernel(
    const int* __restrict__ ids, const float* __restrict__ embed,
    const float* __restrict__ w, const float* __restrict__ b,
    float* __restrict__ out)
{
    const int n = blockIdx.x;
    const int tid = threadIdx.x;
    const int id = ids[n];
    const float4 xv = ((const float4*)(embed + (size_t)id * Hh))[tid];
    float s  = xv.x + xv.y + xv.z + xv.w;
    float sq = xv.x * xv.x + xv.y * xv.y + xv.z * xv.z + xv.w * xv.w;
#pragma unroll
    for (int o = 16; o; o >>= 1) {
        s  += __shfl_xor_sync(0xffffffffu, s,  o);
        sq += __shfl_xor_sync(0xffffffffu, sq, o);
    }
    __shared__ float ss[8], sqs[8];
    if ((tid & 31) == 0) { ss[tid >> 5] = s; sqs[tid >> 5] = sq; }
    __syncthreads();
    s = 0.f; sq = 0.f;
#pragma unroll
    for (int i = 0; i < 8; i++) { s += ss[i]; sq += sqs[i]; }
    const float mu  = s * (1.0f / Hh);
    const float var = sq * (1.0f / Hh) - mu * mu;
    const float rstd = rsqrtf(var + 1e-5f);
    const float4 w4 = ((const float4*)w)[tid];
    const float4 b4 = ((const float4*)b)[tid];
    float4 o4;
    o4.x = (xv.x - mu) * rstd * w4.x + b4.x;
    o4.y = (xv.y - mu) * rstd * w4.y + b4.y;
    o4.z = (xv.z - mu) * rstd * w4.z + b4.z;
    o4.w = (xv.w - mu) * rstd * w4.w + b4.w;
    ((float4*)(out + (size_t)n * Hh))[tid] = o4;
}

// ---------------------------------------------------------------------------
// Token-shift mixing. Outputs rounded to tf32 (GEMM A operands).
// ---------------------------------------------------------------------------
__global__ __launch_bounds__(256) void mix3_kernel(
    const float* __restrict__ x,
    const float* __restrict__ mk, const float* __restrict__ mv, const float* __restrict__ mr,
    float* __restrict__ xk, float* __restrict__ xv, float* __restrict__ xr)
{
    const int idx = blockIdx.x * 256 + threadIdx.x;   // float4 index
    const int n  = idx >> 8;
    const int j4 = idx & 255;
    const int t  = n & (Tt - 1);
    const float4 cur = ((const float4*)x)[idx];
    float4 prev = make_float4(0.f, 0.f, 0.f, 0.f);
    if (t > 0) prev = ((const float4*)x)[idx - 256];
    const float4 k4 = ((const float4*)mk)[j4];
    const float4 v4 = ((const float4*)mv)[j4];
    const float4 r4 = ((const float4*)mr)[j4];
    float4 o;
    o.x = round_tf32(prev.x + k4.x * (cur.x - prev.x));
    o.y = round_tf32(prev.y + k4.y * (cur.y - prev.y));
    o.z = round_tf32(prev.z + k4.z * (cur.z - prev.z));
    o.w = round_tf32(prev.w + k4.w * (cur.w - prev.w));
    ((float4*)xk)[idx] = o;
    o.x = round_tf32(prev.x + v4.x * (cur.x - prev.x));
    o.y = round_tf32(prev.y + v4.y * (cur.y - prev.y));
    o.z = round_tf32(prev.z + v4.z * (cur.z - prev.z));
    o.w = round_tf32(prev.w + v4.w * (cur.w - prev.w));
    ((float4*)xv)[idx] = o;
    o.x = round_tf32(prev.x + r4.x * (cur.x - prev.x));
    o.y = round_tf32(prev.y + r4.y * (cur.y - prev.y));
    o.z = round_tf32(prev.z + r4.z * (cur.z - prev.z));
    o.w = round_tf32(prev.w + r4.w * (cur.w - prev.w));
    ((float4*)xr)[idx] = o;
}

__global__ __launch_bounds__(256) void mix2_kernel(
    const float* __restrict__ x,
    const float* __restrict__ mk, const float* __restrict__ mr,
    float* __restrict__ xk, float* __restrict__ xr)
{
    const int idx = blockIdx.x * 256 + threadIdx.x;
    const int n  = idx >> 8;
    const int j4 = idx & 255;
    const int t  = n & (Tt - 1);
    const float4 cur = ((const float4*)x)[idx];
    float4 prev = make_float4(0.f, 0.f, 0.f, 0.f);
    if (t > 0) prev = ((const float4*)x)[idx - 256];
    const float4 k4 = ((const float4*)mk)[j4];
    const float4 r4 = ((const float4*)mr)[j4];
    float4 o;
    o.x = round_tf32(prev.x + k4.x * (cur.x - prev.x));
    o.y = round_tf32(prev.y + k4.y * (cur.y - prev.y));
    o.z = round_tf32(prev.z + k4.z * (cur.z - prev.z));
    o.w = round_tf32(prev.w + k4.w * (cur.w - prev.w));
    ((float4*)xk)[idx] = o;
    o.x = round_tf32(prev.x + r4.x * (cur.x - prev.x));
    o.y = round_tf32(prev.y + r4.y * (cur.y - prev.y));
    o.z = round_tf32(prev.z + r4.z * (cur.z - prev.z));
    o.w = round_tf32(prev.w + r4.w * (cur.w - prev.w));
    ((float4*)xr)[idx] = o;
}

// ---------------------------------------------------------------------------
// WKV recurrence: one thread per (batch, channel); 128 blocks x 32 threads.
// ---------------------------------------------------------------------------
__global__ __launch_bounds__(32) void wkv_kernel(
    const float* __restrict__ k, const float* __restrict__ v,
    float* __restrict__ y,
    const float* __restrict__ tf, const float* __restrict__ td)
{
    const int idx = blockIdx.x * 32 + threadIdx.x;    // 0..4095
    const int b  = idx >> 10;
    const int ch = idx & (Av - 1);
    const float u = tf[ch];
    const float w = -__expf(td[ch]);
    const float* kp = k + (size_t)b * Tt * Av + ch;
    const float* vp = v + (size_t)b * Tt * Av + ch;
    float*       yp = y + (size_t)b * Tt * Av + ch;
    float aa = 0.f, bb = 0.f, p = -1e38f;
#pragma unroll 4
    for (int t = 0; t < Tt; t++) {
        const float kt = kp[(size_t)t * Av];
        const float vt = vp[(size_t)t * Av];
        const float uk = u + kt;
        const float q  = fmaxf(p, uk);
        const float e1 = __expf(p - q);
        const float e2 = __expf(uk - q);
        yp[(size_t)t * Av] = __fdividef(aa * e1 + e2 * vt, bb * e1 + e2);
        const float pw = p + w;
        const float q2 = fmaxf(pw, kt);
        const float s1 = __expf(pw - q2);
        const float s2 = __expf(kt - q2);
        aa = s1 * aa + s2 * vt;
        bb = s1 * bb + s2;
        p  = q2;
    }
}

// ry = r * y, rounded (GEMM A operand)
__global__ __launch_bounds__(256) void rymul_kernel(
    const float* __restrict__ r, const float* __restrict__ y, float* __restrict__ ry)
{
    const int idx = blockIdx.x * 256 + threadIdx.x;
    const float4 a = ((const float4*)r)[idx];
    const float4 c = ((const float4*)y)[idx];
    float4 o;
    o.x = round_tf32(a.x * c.x); o.y = round_tf32(a.y * c.y);
    o.z = round_tf32(a.z * c.z); o.w = round_tf32(a.w * c.w);
    ((float4*)ry)[idx] = o;
}

// ---------------------------------------------------------------------------
// Tensor-core GEMM (tf32 mma.sync), operands pre-rounded in gmem.
//   C[M,N] (op)= A[M,K] * B[N,K]^T
// CTA 128x128x16, 128 threads = 4 warps, each warp tile 64x64.
// 1.0 LDS per MMA (32 fragment loads / 32 MMAs per 8-deep k-step).
// cp.async 2-stage; GSTRIDE=20 padded smem (conflict-free).
// EPI: 0 store, 1 sigmoid, 2 relu^2 (rounded), 3 C+=acc, 4 C+=S*acc,
//      5 runtime store/sigmoid
// ---------------------------------------------------------------------------
#define GSTRIDE 20

__device__ __forceinline__ void mma_tf32(
    float& d0, float& d1, float& d2, float& d3,
    uint32_t a0, uint32_t a1, uint32_t a2, uint32_t a3,
    uint32_t b0, uint32_t b1)
{
    asm volatile(
        "mma.sync.aligned.m16n8k8.row.col.f32.tf32.tf32.f32 "
        "{%0,%1,%2,%3}, {%4,%5,%6,%7}, {%8,%9}, {%0,%1,%2,%3};\n"
        : "+f"(d0), "+f"(d1), "+f"(d2), "+f"(d3)
        : "r"(a0), "r"(a1), "r"(a2), "r"(a3), "r"(b0), "r"(b1));
}

__device__ __forceinline__ void cp_async16(uint32_t smem, const void* gptr)
{
    asm volatile("cp.async.cg.shared.global [%0], [%1], 16;\n"
                 :: "r"(smem), "l"(gptr));
}

// Load one 128x16 A tile + 128x16 B tile into the given stage (128 threads).
__device__ __forceinline__ void gemm_load_tile(
    const float* Ag, const float* Bg, int K, int kt, int stage,
    int ldr0, int ldc, uint32_t smem_base)
{
    const uint32_t stage_bytes = 2u * 128u * GSTRIDE * 4u;
    const uint32_t opB_bytes   = 128u * GSTRIDE * 4u;
    const int kof = kt * 16 + ldc;
#pragma unroll
    for (int i = 0; i < 4; i++) {
        const int row = ldr0 + i * 32;
        uint32_t da = smem_base + stage * stage_bytes + (uint32_t)(row * GSTRIDE + ldc) * 4u;
        cp_async16(da, Ag + (size_t)row * K + kof);
        cp_async16(da + opB_bytes, Bg + (size_t)row * K + kof);
    }
    asm volatile("cp.async.commit_group;\n");
}

template <int EPI>
__device__ __forceinline__ void gemm_body(
    const float* Ag, const float* Bg, float* C, const float* Sb,
    int N, int K, int bx, int by, bool sig)
{
    __shared__ float sm[2][2][128 * GSTRIDE];

    const int tid  = threadIdx.x;
    const int lane = tid & 31;
    const int w    = tid >> 5;          // 0..3
    const int g    = lane >> 2;         // 0..7
    const int tig  = lane & 3;          // 0..3
    const int mbase = (w >> 1) * 64;    // 0 or 64
    const int nbase = (w & 1) * 64;     // 0 or 64

    const int ldr0 = tid >> 2;          // 0..31 (+32,+64,+96)
    const int ldc  = (tid & 3) * 4;
    const uint32_t smem_base = (uint32_t)__cvta_generic_to_shared(&sm[0][0][0]);

    float acc[4][8][4];
#pragma unroll
    for (int mt = 0; mt < 4; mt++)
#pragma unroll
        for (int nt = 0; nt < 8; nt++)
#pragma unroll
            for (int e = 0; e < 4; e++) acc[mt][nt][e] = 0.f;

    const int KT = K >> 4;

    gemm_load_tile(Ag, Bg, K, 0, 0, ldr0, ldc, smem_base);

    for (int kt = 0; kt < KT; kt++) {
        if (kt + 1 < KT) {
            gemm_load_tile(Ag, Bg, K, kt + 1, (kt + 1) & 1, ldr0, ldc, smem_base);
            asm volatile("cp.async.wait_group 1;\n");
        } else {
            asm volatile("cp.async.wait_group 0;\n");
        }
        __syncthreads();

        const float* As = sm[kt & 1][0];
        const float* Bs = sm[kt & 1][1];
#pragma unroll
        for (int ks = 0; ks < 2; ks++) {
            const int kb = ks * 8;
            uint32_t af[4][4], bf[8][2];
#pragma unroll
            for (int mt = 0; mt < 4; mt++) {
                const int r = mbase + mt * 16 + g;
                af[mt][0] = __float_as_uint(As[r * GSTRIDE + kb + tig]);
                af[mt][1] = __float_as_uint(As[(r + 8) * GSTRIDE + kb + tig]);
                af[mt][2] = __float_as_uint(As[r * GSTRIDE + kb + tig + 4]);
                af[mt][3] = __float_as_uint(As[(r + 8) * GSTRIDE + kb + tig + 4]);
            }
#pragma unroll
            for (int nt = 0; nt < 8; nt++) {
                const int c = nbase + nt * 8 + g;
                bf[nt][0] = __float_as_uint(Bs[c * GSTRIDE + kb + tig]);
                bf[nt][1] = __float_as_uint(Bs[c * GSTRIDE + kb + tig + 4]);
            }
#pragma unroll
            for (int mt = 0; mt < 4; mt++)
#pragma unroll
                for (int nt = 0; nt < 8; nt++)
                    mma_tf32(acc[mt][nt][0], acc[mt][nt][1], acc[mt][nt][2], acc[mt][nt][3],
                             af[mt][0], af[mt][1], af[mt][2], af[mt][3],
                             bf[nt][0], bf[nt][1]);
        }
        __syncthreads();
    }

#pragma unroll
    for (int mt = 0; mt < 4; mt++) {
        const size_t row0 = (size_t)by * 128 + mbase + mt * 16 + g;
#pragma unroll
        for (int nt = 0; nt < 8; nt++) {
            const size_t col = (size_t)bx * 128 + nbase + nt * 8 + 2 * tig;
#pragma unroll
            for (int half = 0; half < 2; half++) {
                const size_t r = row0 + half * 8;
                float v0 = acc[mt][nt][half * 2 + 0];
                float v1 = acc[mt][nt][half * 2 + 1];
                float* cp = C + r * N + col;
                if (EPI == 0) {
                    cp[0] = v0; cp[1] = v1;
                } else if (EPI == 1) {
                    cp[0] = 1.f / (1.f + __expf(-v0));
                    cp[1] = 1.f / (1.f + __expf(-v1));
                } else if (EPI == 2) {
                    float t0 = fmaxf(v0, 0.f), t1 = fmaxf(v1, 0.f);
                    cp[0] = round_tf32(t0 * t0); cp[1] = round_tf32(t1 * t1);
                } else if (EPI == 3) {
                    cp[0] += v0; cp[1] += v1;
                } else if (EPI == 4) {
                    const float* sp = Sb + r * N + col;
                    cp[0] += sp[0] * v0; cp[1] += sp[1] * v1;
                } else { // EPI == 5
                    if (sig) {
                        cp[0] = 1.f / (1.f + __expf(-v0));
                        cp[1] = 1.f / (1.f + __expf(-v1));
                    } else {
                        cp[0] = v0; cp[1] = v1;
                    }
                }
            }
        }
    }
}

template <int EPI>
__global__ __launch_bounds__(128) void gemm_mma(
    const float* __restrict__ A, const float* __restrict__ B,
    float* __restrict__ C, const float* __restrict__ Sb,
    int M, int N, int K)
{
    gemm_body<EPI>(A + (size_t)blockIdx.y * 128 * K,
                   B + (size_t)blockIdx.x * 128 * K,
                   C, Sb, N, K, blockIdx.x, blockIdx.y, false);
}

// Fused k/v/r projection triple: z selects (A,B,C); z==2 applies sigmoid.
__global__ __launch_bounds__(128) void gemm3_mma(
    const float* __restrict__ A0, const float* __restrict__ B0, float* __restrict__ C0,
    const float* __restrict__ A1, const float* __restrict__ B1, float* __restrict__ C1,
    const float* __restrict__ A2, const float* __restrict__ B2, float* __restrict__ C2,
    int N, int K)
{
    const int z = blockIdx.z;
    const float* A; const float* B; float* C;
    if (z == 0)      { A = A0; B = B0; C = C0; }
    else if (z == 1) { A = A1; B = B1; C = C1; }
    else             { A = A2; B = B2; C = C2; }
    gemm_body<5>(A + (size_t)blockIdx.y * 128 * K,
                 B + (size_t)blockIdx.x * 128 * K,
                 C, nullptr, N, K, blockIdx.x, blockIdx.y, z == 2);
}

// ---------------------------------------------------------------------------
// Host launcher
// ---------------------------------------------------------------------------
extern "C" void kernel_launch(void* const* d_in, const int* in_sizes, int n_in,
                              void* d_out, int out_size)
{
    const int*   ids    = (const int*)  d_in[0];
    const float* embed  = (const float*)d_in[1];
    const float* pre_w  = (const float*)d_in[2];
    const float* pre_b  = (const float*)d_in[3];
    const float* post_w = (const float*)d_in[4];
    const float* post_b = (const float*)d_in[5];
    const float* ln1_w  = (const float*)d_in[6];
    const float* ln1_b  = (const float*)d_in[7];
    const float* ln2_w  = (const float*)d_in[8];
    const float* ln2_b  = (const float*)d_in[9];
    const float* amk    = (const float*)d_in[10];
    const float* amv    = (const float*)d_in[11];
    const float* amr    = (const float*)d_in[12];
    const float* awk    = (const float*)d_in[13];
    const float* awv    = (const float*)d_in[14];
    const float* awr    = (const float*)d_in[15];
    const float* awo    = (const float*)d_in[16];
    const float* tdec   = (const float*)d_in[17];
    const float* tfirst = (const float*)d_in[18];
    const float* fmk    = (const float*)d_in[19];
    const float* fmr    = (const float*)d_in[20];
    const float* fwk    = (const float*)d_in[21];
    const float* fwr    = (const float*)d_in[22];
    const float* fwv    = (const float*)d_in[23];

    float* base = nullptr;
    cudaGetSymbolAddress((void**)&base, g_buf);
    float* h   = base;
    float* x   = base + 1 * SROW;
    float* xk  = base + 2 * SROW;
    float* xv  = base + 3 * SROW;
    float* xr  = base + 4 * SROW;
    float* ry  = base + 5 * SROW;
    float* kb  = base + 6 * SROW;
    float* vb  = base + 7 * SROW;
    float* rb  = base + 8 * SROW;
    float* yb  = base + 9 * SROW;
    float* kkb = base + 10 * SROW;

    // rounded weight copies
    const size_t nAH = (size_t)Lv * Av * Hh;   // 6,291,456
    const size_t nIH = (size_t)Lv * Iv * Hh;   // 25,165,824
    float* wawk = base + WOFF;
    float* wawv = wawk + nAH;
    float* wawr = wawv + nAH;
    float* wawo = wawr + nAH;
    float* wfwk = wawo + nAH;
    float* wfwr = wfwk + nIH;
    float* wfwv = wfwr + nAH;

    round4_kernel<<<(int)(nAH / 1024), 256>>>((const float4*)awk, (float4*)wawk);
    round4_kernel<<<(int)(nAH / 1024), 256>>>((const float4*)awv, (float4*)wawv);
    round4_kernel<<<(int)(nAH / 1024), 256>>>((const float4*)awr, (float4*)wawr);
    round4_kernel<<<(int)(nAH / 1024), 256>>>((const float4*)awo, (float4*)wawo);
    round4_kernel<<<(int)(nIH / 1024), 256>>>((const float4*)fwk, (float4*)wfwk);
    round4_kernel<<<(int)(nAH / 1024), 256>>>((const float4*)fwr, (float4*)wfwr);
    round4_kernel<<<(int)(nIH / 1024), 256>>>((const float4*)fwv, (float4*)wfwv);

    const int EW_BLOCKS = (BT * Hh / 4) / 256;   // 8192
    const dim3 gA3(Av / 128, BT / 128, 3);
    const dim3 gH(Hh / 128, BT / 128);
    const dim3 gI(Iv / 128, BT / 128);

    embed_ln_kernel<<<BT, 256>>>(ids, embed, pre_w, pre_b, h);

    for (int i = 0; i < Lv; i++) {
        // --- attention (time mixing) ---
        ln_kernel<<<BT, 256>>>(h, x, ln1_w + i * Hh, ln1_b + i * Hh);
        mix3_kernel<<<EW_BLOCKS, 256>>>(x, amk + i * Hh, amv + i * Hh, amr + i * Hh,
                                        xk, xv, xr);
        gemm3_mma<<<gA3, 128>>>(xk, wawk + (size_t)i * Av * Hh, kb,
                                xv, wawv + (size_t)i * Av * Hh, vb,
                                xr, wawr + (size_t)i * Av * Hh, rb,
                                Av, Hh);
        wkv_kernel<<<128, 32>>>(kb, vb, yb, tfirst + i * Av, tdec + i * Av);
        rymul_kernel<<<EW_BLOCKS, 256>>>(rb, yb, ry);
        gemm_mma<3><<<gH, 128>>>(ry, wawo + (size_t)i * Hh * Av, h, nullptr, BT, Hh, Av);

        // --- feed forward (channel mixing) ---
        ln_kernel<<<BT, 256>>>(h, x, ln2_w + i * Hh, ln2_b + i * Hh);
        mix2_kernel<<<EW_BLOCKS, 256>>>(x, fmk + i * Hh, fmr + i * Hh, xk, xr);
        gemm_mma<2><<<gI, 128>>>(xk, wfwk + (size_t)i * Iv * Hh, kkb, nullptr, BT, Iv, Hh);
        gemm_mma<1><<<gH, 128>>>(xr, wfwr + (size_t)i * Hh * Hh, rb, nullptr, BT, Hh, Hh);
        gemm_mma<4><<<gH, 128>>>(kkb, wfwv + (size_t)i * Hh * Iv, h, rb, BT, Hh, Iv);
    }

    ln_kernel<<<BT, 256>>>(h, (float*)d_out, post_w, post_b);
}